// round 4
// baseline (speedup 1.0000x reference)
#include <cuda_runtime.h>
#include <math.h>

#define HW (1024 * 1024)
#define NPIX4 (HW / 4)          // 262144 = 2^18 float4 per plane
#define NRUNS (HW / 16)         // 65536 16-pixel runs
#define TOTAL_GRAD 5709         // 25+81+289+1089+4225
#define GRID_BLOCKS 592         // 4 per SM * 148 SMs (co-resident guaranteed)

// Scratch (allocation-free: __device__ globals)
__device__ float2       g_grad[TOTAL_GRAD];
__device__ unsigned int g_mink[5];
__device__ unsigned int g_maxk[5];
__device__ float4       g_noise4[NPIX4];   // final noise, pre-multiplied by mix

// software grid barrier state (g_rel is MONOTONIC across graph replays)
__device__ unsigned int g_cnt = 0;
__device__ unsigned int g_rel = 0;

// ---------------------------------------------------------------------------
__device__ __forceinline__ void grid_barrier(unsigned target) {
    __syncthreads();
    if (threadIdx.x == 0) {
        __threadfence();                      // release: publish this block's writes
        unsigned old = atomicAdd(&g_cnt, 1);
        if (old == gridDim.x - 1) {
            atomicExch(&g_cnt, 0);            // reset for next barrier/replay
            __threadfence();
            atomicAdd(&g_rel, 1);             // release everyone
        } else {
            while (*((volatile unsigned*)&g_rel) < target) { __nanosleep(32); }
        }
        __threadfence();                      // acquire
    }
    __syncthreads();
}

// ---------------------------------------------------------------------------
// order-preserving float <-> uint encoding for atomic min/max
// ---------------------------------------------------------------------------
__device__ __forceinline__ unsigned enc(float f) {
    unsigned u = __float_as_uint(f);
    return (u & 0x80000000u) ? ~u : (u | 0x80000000u);
}
__device__ __forceinline__ float dec(unsigned u) {
    return (u & 0x80000000u) ? __uint_as_float(u ^ 0x80000000u)
                             : __uint_as_float(~u);
}

// ---------------------------------------------------------------------------
// Per-run (16 aligned pixels, same row => single cell in every octave)
// hoisted Perlin constants.  n(j) = t0 + wx*t1,
//   t0 = C0 + P1*D0,  t1 = E + P1*F
// ---------------------------------------------------------------------------
struct RunConst { float C0, D0, E, F; };

template <int O>
__device__ __forceinline__ RunConst run_const(int i, int j0) {
    constexpr int RES = 4 << O;
    constexpr int SH  = 8 - O;
    constexpr int OFFS[5] = {0, 25, 106, 395, 1484};
    const float delta = (float)RES / 1023.0f;

    float vy = (float)i * delta;
    float P0 = vy - floorf(vy);
    float wy = P0 * P0 * (3.0f - 2.0f * P0);

    int cy = i >> SH, cx = j0 >> SH;
    const float2* g = g_grad + OFFS[O];
    float2 g00 = g[cy * (RES + 1) + cx];
    float2 g10 = g[(cy + 1) * (RES + 1) + cx];
    float2 g01 = g[cy * (RES + 1) + cx + 1];
    float2 g11 = g[(cy + 1) * (RES + 1) + cx + 1];

    float A0 = P0 * g00.x;
    float A1 = (P0 - 1.0f) * g10.x;
    float B0 = P0 * g01.x - g01.y;
    float B1 = (P0 - 1.0f) * g11.x - g11.y;

    float C0 = A0 + wy * (A1 - A0);
    float D0 = g00.y + wy * (g10.y - g00.y);
    float C1 = B0 + wy * (B1 - B0);
    float D1 = g01.y + wy * (g11.y - g01.y);

    RunConst rc;
    rc.C0 = C0; rc.D0 = D0; rc.E = C1 - C0; rc.F = D1 - D0;
    return rc;
}

template <int O>
__device__ __forceinline__ float run_eval(const RunConst& rc, int j) {
    constexpr int RES = 4 << O;
    const float delta = (float)RES / 1023.0f;
    float vx = (float)j * delta;
    float P1 = vx - floorf(vx);
    float wx = P1 * P1 * (3.0f - 2.0f * P1);
    float t0 = fmaf(P1, rc.D0, rc.C0);
    float t1 = fmaf(P1, rc.F, rc.E);
    return fmaf(wx, t1, t0);
}

// ---------------------------------------------------------------------------
// Single fused persistent kernel:
//   Phase 0: gradient tables + min/max reset
//   Phase 1: per-octave global min/max
//   Phase 2: noise plane (normalized, * mix)
//   Phase 3: streaming apply out = clip(img + noise, 0, 1)
// ---------------------------------------------------------------------------
__global__ void __launch_bounds__(256, 4) k_fused(
    const float* __restrict__ a0, const float* __restrict__ a1,
    const float* __restrict__ a2, const float* __restrict__ a3,
    const float* __restrict__ a4, const float* __restrict__ mixp,
    const float4* __restrict__ img, float4* __restrict__ out, int n4)
{
    __shared__ unsigned s_r0;
    if (threadIdx.x == 0) s_r0 = *((volatile unsigned*)&g_rel);

    int gtid = blockIdx.x * 256 + threadIdx.x;
    int nthreads = gridDim.x * 256;

    // ---- Phase 0: reset min/max + build gradient tables -------------------
    if (gtid < 5) { g_mink[gtid] = 0xFFFFFFFFu; g_maxk[gtid] = 0u; }
    {
        const float* angs[5] = {a0, a1, a2, a3, a4};
        const int cnt[5] = {25, 81, 289, 1089, 4225};
        for (int idx = gtid; idx < TOTAL_GRAD; idx += nthreads) {
            int o = 0, rem = idx;
            while (o < 4 && rem >= cnt[o]) { rem -= cnt[o]; o++; }
            float a = angs[o][rem];
            float s, c;
            sincosf(a, &s, &c);
            g_grad[idx] = make_float2(c, s);
        }
    }
    __syncthreads();
    unsigned R0 = s_r0;
    grid_barrier(R0 + 1);

    // ---- Phase 1: min/max over runs (blocks 0..255 fully active) ----------
    if (gtid < NRUNS) {
        int i  = gtid >> 6;
        int j0 = (gtid & 63) << 4;

        RunConst r0 = run_const<0>(i, j0);
        RunConst r1 = run_const<1>(i, j0);
        RunConst r2 = run_const<2>(i, j0);
        RunConst r3 = run_const<3>(i, j0);
        RunConst r4 = run_const<4>(i, j0);

        float mn[5], mx[5];
#pragma unroll
        for (int o = 0; o < 5; o++) { mn[o] = INFINITY; mx[o] = -INFINITY; }

#pragma unroll
        for (int k = 0; k < 16; k++) {
            int j = j0 + k;
            float n;
            n = run_eval<0>(r0, j); mn[0] = fminf(mn[0], n); mx[0] = fmaxf(mx[0], n);
            n = run_eval<1>(r1, j); mn[1] = fminf(mn[1], n); mx[1] = fmaxf(mx[1], n);
            n = run_eval<2>(r2, j); mn[2] = fminf(mn[2], n); mx[2] = fmaxf(mx[2], n);
            n = run_eval<3>(r3, j); mn[3] = fminf(mn[3], n); mx[3] = fmaxf(mx[3], n);
            n = run_eval<4>(r4, j); mn[4] = fminf(mn[4], n); mx[4] = fmaxf(mx[4], n);
        }

        // warp reduce
#pragma unroll
        for (int o = 0; o < 5; o++) {
#pragma unroll
            for (int d = 16; d > 0; d >>= 1) {
                mn[o] = fminf(mn[o], __shfl_xor_sync(0xFFFFFFFFu, mn[o], d));
                mx[o] = fmaxf(mx[o], __shfl_xor_sync(0xFFFFFFFFu, mx[o], d));
            }
        }

        __shared__ float smn[5][8], smx[5][8];
        int w = threadIdx.x >> 5, lane = threadIdx.x & 31;
        if (lane == 0) {
#pragma unroll
            for (int o = 0; o < 5; o++) { smn[o][w] = mn[o]; smx[o][w] = mx[o]; }
        }
        __syncthreads();
        if (threadIdx.x == 0) {
#pragma unroll
            for (int o = 0; o < 5; o++) {
                float a = smn[o][0], b = smx[o][0];
#pragma unroll
                for (int k = 1; k < 8; k++) { a = fminf(a, smn[o][k]); b = fmaxf(b, smx[o][k]); }
                atomicMin(&g_mink[o], enc(a));
                atomicMax(&g_maxk[o], enc(b));
            }
        }
    }
    grid_barrier(R0 + 2);

    // ---- Phase 2: noise plane (normalized, pre-multiplied by mix) ---------
    if (gtid < NRUNS) {
        int i  = gtid >> 6;
        int j0 = (gtid & 63) << 4;

        float mixv = *mixp;
        const float amps[5] = {0.1f, 0.05f, 0.025f, 0.0125f, 0.00625f};
        float s[5], B = 0.0f;
#pragma unroll
        for (int o = 0; o < 5; o++) {
            float mnv = dec(g_mink[o]), mxv = dec(g_maxk[o]);
            float inv = 1.0f / (mxv - mnv);
            float am = amps[o] * mixv;
            s[o] = 2.0f * am * inv;
            B += am * (-2.0f * mnv * inv - 1.0f);
        }

        RunConst r0 = run_const<0>(i, j0);
        RunConst r1 = run_const<1>(i, j0);
        RunConst r2 = run_const<2>(i, j0);
        RunConst r3 = run_const<3>(i, j0);
        RunConst r4 = run_const<4>(i, j0);

        int p4 = gtid << 2;
#pragma unroll
        for (int q = 0; q < 4; q++) {
            float v[4];
#pragma unroll
            for (int k = 0; k < 4; k++) {
                int j = j0 + q * 4 + k;
                float acc = B;
                acc = fmaf(run_eval<0>(r0, j), s[0], acc);
                acc = fmaf(run_eval<1>(r1, j), s[1], acc);
                acc = fmaf(run_eval<2>(r2, j), s[2], acc);
                acc = fmaf(run_eval<3>(r3, j), s[3], acc);
                acc = fmaf(run_eval<4>(r4, j), s[4], acc);
                v[k] = acc;
            }
            g_noise4[p4 + q] = make_float4(v[0], v[1], v[2], v[3]);
        }
    }
    grid_barrier(R0 + 3);

    // ---- Phase 3: streaming apply (chunk-strided, 4 float4/thread) --------
    int nchunks = (n4 + 1023) >> 10;   // 1024 float4 per chunk
    for (int c = blockIdx.x; c < nchunks; c += gridDim.x) {
        int base = (c << 10) + threadIdx.x;

        if (base + 768 < n4) {
            float4 v0 = __ldcs(img + base);
            float4 v1 = __ldcs(img + base + 256);
            float4 v2 = __ldcs(img + base + 512);
            float4 v3 = __ldcs(img + base + 768);
            float4 n0 = g_noise4[(base)       & (NPIX4 - 1)];
            float4 n1 = g_noise4[(base + 256) & (NPIX4 - 1)];
            float4 n2 = g_noise4[(base + 512) & (NPIX4 - 1)];
            float4 n3 = g_noise4[(base + 768) & (NPIX4 - 1)];

            v0.x = fminf(fmaxf(v0.x + n0.x, 0.0f), 1.0f);
            v0.y = fminf(fmaxf(v0.y + n0.y, 0.0f), 1.0f);
            v0.z = fminf(fmaxf(v0.z + n0.z, 0.0f), 1.0f);
            v0.w = fminf(fmaxf(v0.w + n0.w, 0.0f), 1.0f);
            v1.x = fminf(fmaxf(v1.x + n1.x, 0.0f), 1.0f);
            v1.y = fminf(fmaxf(v1.y + n1.y, 0.0f), 1.0f);
            v1.z = fminf(fmaxf(v1.z + n1.z, 0.0f), 1.0f);
            v1.w = fminf(fmaxf(v1.w + n1.w, 0.0f), 1.0f);
            v2.x = fminf(fmaxf(v2.x + n2.x, 0.0f), 1.0f);
            v2.y = fminf(fmaxf(v2.y + n2.y, 0.0f), 1.0f);
            v2.z = fminf(fmaxf(v2.z + n2.z, 0.0f), 1.0f);
            v2.w = fminf(fmaxf(v2.w + n2.w, 0.0f), 1.0f);
            v3.x = fminf(fmaxf(v3.x + n3.x, 0.0f), 1.0f);
            v3.y = fminf(fmaxf(v3.y + n3.y, 0.0f), 1.0f);
            v3.z = fminf(fmaxf(v3.z + n3.z, 0.0f), 1.0f);
            v3.w = fminf(fmaxf(v3.w + n3.w, 0.0f), 1.0f);

            __stcs(out + base,       v0);
            __stcs(out + base + 256, v1);
            __stcs(out + base + 512, v2);
            __stcs(out + base + 768, v3);
        } else {
            for (int k = 0; k < 4; k++) {
                int idx = base + k * 256;
                if (idx >= n4) break;
                float4 nz = g_noise4[idx & (NPIX4 - 1)];
                float4 v = __ldcs(img + idx);
                v.x = fminf(fmaxf(v.x + nz.x, 0.0f), 1.0f);
                v.y = fminf(fmaxf(v.y + nz.y, 0.0f), 1.0f);
                v.z = fminf(fmaxf(v.z + nz.z, 0.0f), 1.0f);
                v.w = fminf(fmaxf(v.w + nz.w, 0.0f), 1.0f);
                __stcs(out + idx, v);
            }
        }
    }
}

// ---------------------------------------------------------------------------
extern "C" void kernel_launch(void* const* d_in, const int* in_sizes, int n_in,
                              void* d_out, int out_size) {
    const float* image = nullptr;
    const float* mixp  = nullptr;
    const float* ang[5] = {nullptr, nullptr, nullptr, nullptr, nullptr};

    for (int k = 0; k < n_in; k++) {
        int s = in_sizes[k];
        const float* p = (const float*)d_in[k];
        if      (s == 1)    mixp   = p;
        else if (s == 25)   ang[0] = p;
        else if (s == 81)   ang[1] = p;
        else if (s == 289)  ang[2] = p;
        else if (s == 1089) ang[3] = p;
        else if (s == 4225) ang[4] = p;
        else                image  = p;   // 16*3*1024*1024
    }

    int n4 = out_size / 4;
    k_fused<<<GRID_BLOCKS, 256>>>(ang[0], ang[1], ang[2], ang[3], ang[4],
                                  mixp, (const float4*)image, (float4*)d_out, n4);
}

// round 5
// speedup vs baseline: 1.1009x; 1.1009x over previous
#include <cuda_runtime.h>
#include <math.h>

#define HW (1024 * 1024)
#define NPIX4 (HW / 4)          // 262144 float4 per plane
#define NRUNS (HW / 16)         // 65536 16-pixel runs
#define TOTAL_GRAD 5709         // 25+81+289+1089+4225

// Scratch (allocation-free: __device__ globals)
__device__ float2       g_grad[TOTAL_GRAD];
__device__ unsigned int g_mink[5];
__device__ unsigned int g_maxk[5];

// ---------------------------------------------------------------------------
// order-preserving float <-> uint encoding for atomic min/max
// ---------------------------------------------------------------------------
__device__ __forceinline__ unsigned enc(float f) {
    unsigned u = __float_as_uint(f);
    return (u & 0x80000000u) ? ~u : (u | 0x80000000u);
}
__device__ __forceinline__ float dec(unsigned u) {
    return (u & 0x80000000u) ? __uint_as_float(u ^ 0x80000000u)
                             : __uint_as_float(~u);
}

// ---------------------------------------------------------------------------
// Per-run (aligned pixels, same row, single cell in every octave)
// hoisted Perlin constants.  n(j) = t0 + wx*t1,
//   t0 = C0 + P1*D0,  t1 = E + P1*F
// Valid when all pixels j0..j0+len-1 share a cell at octave O (len<=16, aligned).
// ---------------------------------------------------------------------------
struct RunConst { float C0, D0, E, F; };

template <int O>
__device__ __forceinline__ RunConst run_const(int i, int j0) {
    constexpr int RES = 4 << O;
    constexpr int SH  = 8 - O;
    constexpr int OFFS[5] = {0, 25, 106, 395, 1484};
    const float delta = (float)RES / 1023.0f;

    float vy = (float)i * delta;
    float P0 = vy - floorf(vy);
    float wy = P0 * P0 * (3.0f - 2.0f * P0);

    int cy = i >> SH, cx = j0 >> SH;
    const float2* g = g_grad + OFFS[O];
    float2 g00 = g[cy * (RES + 1) + cx];
    float2 g10 = g[(cy + 1) * (RES + 1) + cx];
    float2 g01 = g[cy * (RES + 1) + cx + 1];
    float2 g11 = g[(cy + 1) * (RES + 1) + cx + 1];

    float A0 = P0 * g00.x;
    float A1 = (P0 - 1.0f) * g10.x;
    float B0 = P0 * g01.x - g01.y;
    float B1 = (P0 - 1.0f) * g11.x - g11.y;

    float C0 = A0 + wy * (A1 - A0);
    float D0 = g00.y + wy * (g10.y - g00.y);
    float C1 = B0 + wy * (B1 - B0);
    float D1 = g01.y + wy * (g11.y - g01.y);

    RunConst rc;
    rc.C0 = C0; rc.D0 = D0; rc.E = C1 - C0; rc.F = D1 - D0;
    return rc;
}

template <int O>
__device__ __forceinline__ float run_eval(const RunConst& rc, int j) {
    constexpr int RES = 4 << O;
    const float delta = (float)RES / 1023.0f;
    float vx = (float)j * delta;
    float P1 = vx - floorf(vx);
    float wx = P1 * P1 * (3.0f - 2.0f * P1);
    float t0 = fmaf(P1, rc.D0, rc.C0);
    float t1 = fmaf(P1, rc.F, rc.E);
    return fmaf(wx, t1, t0);
}

// ---------------------------------------------------------------------------
// K1: build gradient tables + reset min/max (must happen each replay)
// ---------------------------------------------------------------------------
__global__ void k_setup(const float* __restrict__ a0, const float* __restrict__ a1,
                        const float* __restrict__ a2, const float* __restrict__ a3,
                        const float* __restrict__ a4) {
    int t = blockIdx.x * blockDim.x + threadIdx.x;
    if (blockIdx.x == 0 && threadIdx.x < 5) {
        g_mink[threadIdx.x] = 0xFFFFFFFFu;
        g_maxk[threadIdx.x] = 0u;
    }
    const float* angs[5] = {a0, a1, a2, a3, a4};
    const int cnt[5] = {25, 81, 289, 1089, 4225};
    for (int idx = t; idx < TOTAL_GRAD; idx += gridDim.x * blockDim.x) {
        int o = 0, rem = idx;
        while (o < 4 && rem >= cnt[o]) { rem -= cnt[o]; o++; }
        float a = angs[o][rem];
        float s, c;
        sincosf(a, &s, &c);
        g_grad[idx] = make_float2(c, s);
    }
}

// ---------------------------------------------------------------------------
// K2: global min/max per octave.  One thread = one 16-pixel run.
// ---------------------------------------------------------------------------
__global__ void __launch_bounds__(256) k_minmax() {
    int t = blockIdx.x * blockDim.x + threadIdx.x;   // 0..65535
    int i  = t >> 6;
    int j0 = (t & 63) << 4;

    RunConst r0 = run_const<0>(i, j0);
    RunConst r1 = run_const<1>(i, j0);
    RunConst r2 = run_const<2>(i, j0);
    RunConst r3 = run_const<3>(i, j0);
    RunConst r4 = run_const<4>(i, j0);

    float mn[5], mx[5];
#pragma unroll
    for (int o = 0; o < 5; o++) { mn[o] = INFINITY; mx[o] = -INFINITY; }

#pragma unroll
    for (int k = 0; k < 16; k++) {
        int j = j0 + k;
        float n;
        n = run_eval<0>(r0, j); mn[0] = fminf(mn[0], n); mx[0] = fmaxf(mx[0], n);
        n = run_eval<1>(r1, j); mn[1] = fminf(mn[1], n); mx[1] = fmaxf(mx[1], n);
        n = run_eval<2>(r2, j); mn[2] = fminf(mn[2], n); mx[2] = fmaxf(mx[2], n);
        n = run_eval<3>(r3, j); mn[3] = fminf(mn[3], n); mx[3] = fmaxf(mx[3], n);
        n = run_eval<4>(r4, j); mn[4] = fminf(mn[4], n); mx[4] = fmaxf(mx[4], n);
    }

    // warp reduce
#pragma unroll
    for (int o = 0; o < 5; o++) {
#pragma unroll
        for (int d = 16; d > 0; d >>= 1) {
            mn[o] = fminf(mn[o], __shfl_xor_sync(0xFFFFFFFFu, mn[o], d));
            mx[o] = fmaxf(mx[o], __shfl_xor_sync(0xFFFFFFFFu, mx[o], d));
        }
    }

    __shared__ float smn[5][8], smx[5][8];
    int w = threadIdx.x >> 5, lane = threadIdx.x & 31;
    if (lane == 0) {
#pragma unroll
        for (int o = 0; o < 5; o++) { smn[o][w] = mn[o]; smx[o][w] = mx[o]; }
    }
    __syncthreads();
    if (threadIdx.x == 0) {
#pragma unroll
        for (int o = 0; o < 5; o++) {
            float a = smn[o][0], b = smx[o][0];
#pragma unroll
            for (int k = 1; k < 8; k++) { a = fminf(a, smn[o][k]); b = fmaxf(b, smx[o][k]); }
            atomicMin(&g_mink[o], enc(a));
            atomicMax(&g_maxk[o], enc(b));
        }
    }
}

// ---------------------------------------------------------------------------
// K3 (fused noise+apply): each thread owns one float4 pixel-group (4 pixels,
// same row, same cell at every octave since j0 is 4-aligned and cells are
// >=16 wide).  Noise computed ONCE in registers, then the thread streams all
// 48 batch/channel planes: out = clip(img + noise, 0, 1).
// ---------------------------------------------------------------------------
__global__ void __launch_bounds__(256) k_apply(const float4* __restrict__ img,
                                               float4* __restrict__ out,
                                               const float* __restrict__ mixp,
                                               int nplanes) {
    int g = blockIdx.x * 256 + threadIdx.x;          // 0..NPIX4-1
    int pix = g << 2;
    int i = pix >> 10, j0 = pix & 1023;

    // normalization folded to scale/bias (per octave), mix pre-multiplied
    float mixv = *mixp;
    const float amps[5] = {0.1f, 0.05f, 0.025f, 0.0125f, 0.00625f};
    float s[5], B = 0.0f;
#pragma unroll
    for (int o = 0; o < 5; o++) {
        float mnv = dec(g_mink[o]), mxv = dec(g_maxk[o]);
        float inv = 1.0f / (mxv - mnv);
        float am = amps[o] * mixv;
        s[o] = 2.0f * am * inv;
        B += am * (-2.0f * mnv * inv - 1.0f);
    }

    RunConst r0 = run_const<0>(i, j0);
    RunConst r1 = run_const<1>(i, j0);
    RunConst r2 = run_const<2>(i, j0);
    RunConst r3 = run_const<3>(i, j0);
    RunConst r4 = run_const<4>(i, j0);

    float nz[4];
#pragma unroll
    for (int k = 0; k < 4; k++) {
        int j = j0 + k;
        float acc = B;
        acc = fmaf(run_eval<0>(r0, j), s[0], acc);
        acc = fmaf(run_eval<1>(r1, j), s[1], acc);
        acc = fmaf(run_eval<2>(r2, j), s[2], acc);
        acc = fmaf(run_eval<3>(r3, j), s[3], acc);
        acc = fmaf(run_eval<4>(r4, j), s[4], acc);
        nz[k] = acc;
    }

    const float4* ip = img + g;
    float4*       op = out + g;

    // stream planes, 4 at a time with front-batched loads for MLP
#pragma unroll 1
    for (int p = 0; p + 3 < nplanes; p += 4) {
        float4 v0 = __ldcs(ip + (p    ) * NPIX4);
        float4 v1 = __ldcs(ip + (p + 1) * NPIX4);
        float4 v2 = __ldcs(ip + (p + 2) * NPIX4);
        float4 v3 = __ldcs(ip + (p + 3) * NPIX4);

        v0.x = fminf(fmaxf(v0.x + nz[0], 0.0f), 1.0f);
        v0.y = fminf(fmaxf(v0.y + nz[1], 0.0f), 1.0f);
        v0.z = fminf(fmaxf(v0.z + nz[2], 0.0f), 1.0f);
        v0.w = fminf(fmaxf(v0.w + nz[3], 0.0f), 1.0f);
        v1.x = fminf(fmaxf(v1.x + nz[0], 0.0f), 1.0f);
        v1.y = fminf(fmaxf(v1.y + nz[1], 0.0f), 1.0f);
        v1.z = fminf(fmaxf(v1.z + nz[2], 0.0f), 1.0f);
        v1.w = fminf(fmaxf(v1.w + nz[3], 0.0f), 1.0f);
        v2.x = fminf(fmaxf(v2.x + nz[0], 0.0f), 1.0f);
        v2.y = fminf(fmaxf(v2.y + nz[1], 0.0f), 1.0f);
        v2.z = fminf(fmaxf(v2.z + nz[2], 0.0f), 1.0f);
        v2.w = fminf(fmaxf(v2.w + nz[3], 0.0f), 1.0f);
        v3.x = fminf(fmaxf(v3.x + nz[0], 0.0f), 1.0f);
        v3.y = fminf(fmaxf(v3.y + nz[1], 0.0f), 1.0f);
        v3.z = fminf(fmaxf(v3.z + nz[2], 0.0f), 1.0f);
        v3.w = fminf(fmaxf(v3.w + nz[3], 0.0f), 1.0f);

        __stcs(op + (p    ) * NPIX4, v0);
        __stcs(op + (p + 1) * NPIX4, v1);
        __stcs(op + (p + 2) * NPIX4, v2);
        __stcs(op + (p + 3) * NPIX4, v3);
    }
    // tail planes (nplanes=48 -> not taken, kept for safety)
    for (int p = nplanes & ~3; p < nplanes; p++) {
        float4 v = __ldcs(ip + p * NPIX4);
        v.x = fminf(fmaxf(v.x + nz[0], 0.0f), 1.0f);
        v.y = fminf(fmaxf(v.y + nz[1], 0.0f), 1.0f);
        v.z = fminf(fmaxf(v.z + nz[2], 0.0f), 1.0f);
        v.w = fminf(fmaxf(v.w + nz[3], 0.0f), 1.0f);
        __stcs(op + p * NPIX4, v);
    }
}

// ---------------------------------------------------------------------------
extern "C" void kernel_launch(void* const* d_in, const int* in_sizes, int n_in,
                              void* d_out, int out_size) {
    const float* image = nullptr;
    const float* mixp  = nullptr;
    const float* ang[5] = {nullptr, nullptr, nullptr, nullptr, nullptr};

    for (int k = 0; k < n_in; k++) {
        int s = in_sizes[k];
        const float* p = (const float*)d_in[k];
        if      (s == 1)    mixp   = p;
        else if (s == 25)   ang[0] = p;
        else if (s == 81)   ang[1] = p;
        else if (s == 289)  ang[2] = p;
        else if (s == 1089) ang[3] = p;
        else if (s == 4225) ang[4] = p;
        else                image  = p;   // 16*3*1024*1024
    }

    int nplanes = (out_size / 4) / NPIX4;   // 48

    k_setup<<<23, 256>>>(ang[0], ang[1], ang[2], ang[3], ang[4]);
    k_minmax<<<NRUNS / 256, 256>>>();
    k_apply<<<NPIX4 / 256, 256>>>((const float4*)image, (float4*)d_out,
                                  mixp, nplanes);
}

// round 6
// speedup vs baseline: 1.1622x; 1.0557x over previous
#include <cuda_runtime.h>
#include <math.h>

#define HW (1024 * 1024)
#define NPIX4 (HW / 4)          // 262144 float4 per plane
#define NRUNS (HW / 16)         // 65536 16-pixel runs
#define NBLK  (NRUNS / 256)     // 256 blocks for minmax/noise
#define NGRAD_SM 258            // per-block gradients: sum 2*(RES+1)

// Scratch (allocation-free: __device__ globals)
__device__ float  g_bmn[5][NBLK];   // per-block partial minima (rewritten each run)
__device__ float  g_bmx[5][NBLK];   // per-block partial maxima
__device__ float4 g_noise4[NPIX4];  // final noise, pre-multiplied by mix

// ---------------------------------------------------------------------------
// Per-run (16 aligned pixels, same row => single cell in every octave)
// hoisted Perlin constants.  n(j) = t0 + wx*t1,
//   t0 = C0 + P1*D0,  t1 = E + P1*F
// Gradients come from block-shared memory (2 rows x (RES+1) per octave).
// ---------------------------------------------------------------------------
struct RunConst { float C0, D0, E, F; };

// smem layout offsets (float2 units) per octave: 2*(RES+1) each
// O0:0  O1:10  O2:28  O3:62  O4:128   total 258

template <int O>
__device__ __forceinline__ RunConst run_const_sm(const float2* sg, int i, int j0) {
    constexpr int RES = 4 << O;
    constexpr int SH  = 8 - O;
    constexpr int SOFF[5] = {0, 10, 28, 62, 128};
    const float delta = (float)RES / 1023.0f;

    float vy = (float)i * delta;
    float P0 = vy - floorf(vy);
    float wy = P0 * P0 * (3.0f - 2.0f * P0);

    int cx = j0 >> SH;
    const float2* g = sg + SOFF[O];
    float2 g00 = g[cx];
    float2 g10 = g[(RES + 1) + cx];
    float2 g01 = g[cx + 1];
    float2 g11 = g[(RES + 1) + cx + 1];

    float A0 = P0 * g00.x;
    float A1 = (P0 - 1.0f) * g10.x;
    float B0 = P0 * g01.x - g01.y;
    float B1 = (P0 - 1.0f) * g11.x - g11.y;

    float C0 = A0 + wy * (A1 - A0);
    float D0 = g00.y + wy * (g10.y - g00.y);
    float C1 = B0 + wy * (B1 - B0);
    float D1 = g01.y + wy * (g11.y - g01.y);

    RunConst rc;
    rc.C0 = C0; rc.D0 = D0; rc.E = C1 - C0; rc.F = D1 - D0;
    return rc;
}

template <int O>
__device__ __forceinline__ float run_eval(const RunConst& rc, int j) {
    constexpr int RES = 4 << O;
    const float delta = (float)RES / 1023.0f;
    float vx = (float)j * delta;
    float P1 = vx - floorf(vx);
    float wx = P1 * P1 * (3.0f - 2.0f * P1);
    float t0 = fmaf(P1, rc.D0, rc.C0);
    float t1 = fmaf(P1, rc.F, rc.E);
    return fmaf(wx, t1, t0);
}

// ---------------------------------------------------------------------------
// Fill the block's gradient smem table: 2 rows x (RES+1) cos/sin per octave.
// Block covers rows i0..i0+3 (i0 = 4*blockIdx), which share one cell-row
// at every octave (cell height >= 16, i0 4-aligned).
// ---------------------------------------------------------------------------
__device__ __forceinline__ void fill_grad_sm(
    float2* sg, int i0,
    const float* a0, const float* a1, const float* a2,
    const float* a3, const float* a4)
{
    const float* angs[5] = {a0, a1, a2, a3, a4};
#pragma unroll
    for (int rep = 0; rep < 2; rep++) {
        int idx = threadIdx.x + rep * 256;
        if (idx < NGRAD_SM) {
            int o, local;
            if      (idx < 10)  { o = 0; local = idx; }
            else if (idx < 28)  { o = 1; local = idx - 10; }
            else if (idx < 62)  { o = 2; local = idx - 28; }
            else if (idx < 128) { o = 3; local = idx - 62; }
            else                { o = 4; local = idx - 128; }
            int W  = (4 << o) + 1;
            int SH = 8 - o;
            int row = local / W, cx = local - row * W;
            int cy0 = i0 >> SH;
            float a = angs[o][(cy0 + row) * W + cx];
            float s, c;
            sincosf(a, &s, &c);
            sg[idx] = make_float2(c, s);
        }
    }
}

// ---------------------------------------------------------------------------
// K1: per-octave min/max partials. One thread = one 16-pixel run.
// Gradients computed in-block (sincos -> smem). No global table, no reset.
// ---------------------------------------------------------------------------
__global__ void __launch_bounds__(256) k_minmax(
    const float* __restrict__ a0, const float* __restrict__ a1,
    const float* __restrict__ a2, const float* __restrict__ a3,
    const float* __restrict__ a4)
{
    __shared__ float2 sgrad[NGRAD_SM];
    int i0 = blockIdx.x * 4;
    fill_grad_sm(sgrad, i0, a0, a1, a2, a3, a4);
    __syncthreads();

    int t = blockIdx.x * 256 + threadIdx.x;   // 0..65535
    int i  = t >> 6;
    int j0 = (t & 63) << 4;

    RunConst r0 = run_const_sm<0>(sgrad, i, j0);
    RunConst r1 = run_const_sm<1>(sgrad, i, j0);
    RunConst r2 = run_const_sm<2>(sgrad, i, j0);
    RunConst r3 = run_const_sm<3>(sgrad, i, j0);
    RunConst r4 = run_const_sm<4>(sgrad, i, j0);

    float mn[5], mx[5];
#pragma unroll
    for (int o = 0; o < 5; o++) { mn[o] = INFINITY; mx[o] = -INFINITY; }

#pragma unroll
    for (int k = 0; k < 16; k++) {
        int j = j0 + k;
        float n;
        n = run_eval<0>(r0, j); mn[0] = fminf(mn[0], n); mx[0] = fmaxf(mx[0], n);
        n = run_eval<1>(r1, j); mn[1] = fminf(mn[1], n); mx[1] = fmaxf(mx[1], n);
        n = run_eval<2>(r2, j); mn[2] = fminf(mn[2], n); mx[2] = fmaxf(mx[2], n);
        n = run_eval<3>(r3, j); mn[3] = fminf(mn[3], n); mx[3] = fmaxf(mx[3], n);
        n = run_eval<4>(r4, j); mn[4] = fminf(mn[4], n); mx[4] = fmaxf(mx[4], n);
    }

    // warp reduce
#pragma unroll
    for (int o = 0; o < 5; o++) {
#pragma unroll
        for (int d = 16; d > 0; d >>= 1) {
            mn[o] = fminf(mn[o], __shfl_xor_sync(0xFFFFFFFFu, mn[o], d));
            mx[o] = fmaxf(mx[o], __shfl_xor_sync(0xFFFFFFFFu, mx[o], d));
        }
    }

    __shared__ float smn[5][8], smx[5][8];
    int w = threadIdx.x >> 5, lane = threadIdx.x & 31;
    if (lane == 0) {
#pragma unroll
        for (int o = 0; o < 5; o++) { smn[o][w] = mn[o]; smx[o][w] = mx[o]; }
    }
    __syncthreads();
    if (threadIdx.x < 5) {
        int o = threadIdx.x;
        float a = smn[o][0], b = smx[o][0];
#pragma unroll
        for (int k = 1; k < 8; k++) { a = fminf(a, smn[o][k]); b = fmaxf(b, smx[o][k]); }
        g_bmn[o][blockIdx.x] = a;
        g_bmx[o][blockIdx.x] = b;
    }
}

// ---------------------------------------------------------------------------
// K2: reduce partials -> normalized multi-octave noise * mix.
// One thread = one 16-pixel run; gradients in-block like K1.
// ---------------------------------------------------------------------------
__global__ void __launch_bounds__(256) k_noise(
    const float* __restrict__ a0, const float* __restrict__ a1,
    const float* __restrict__ a2, const float* __restrict__ a3,
    const float* __restrict__ a4, const float* __restrict__ mixp)
{
    __shared__ float2 sgrad[NGRAD_SM];
    __shared__ float smn[5][8], smx[5][8];
    __shared__ float fmn[5], fmx[5];

    int i0 = blockIdx.x * 4;
    fill_grad_sm(sgrad, i0, a0, a1, a2, a3, a4);

    // reduce the 256 per-block partials (one partial per thread)
    int w = threadIdx.x >> 5, lane = threadIdx.x & 31;
    {
        float pm[5], px[5];
#pragma unroll
        for (int o = 0; o < 5; o++) {
            pm[o] = g_bmn[o][threadIdx.x];
            px[o] = g_bmx[o][threadIdx.x];
        }
#pragma unroll
        for (int o = 0; o < 5; o++) {
#pragma unroll
            for (int d = 16; d > 0; d >>= 1) {
                pm[o] = fminf(pm[o], __shfl_xor_sync(0xFFFFFFFFu, pm[o], d));
                px[o] = fmaxf(px[o], __shfl_xor_sync(0xFFFFFFFFu, px[o], d));
            }
        }
        if (lane == 0) {
#pragma unroll
            for (int o = 0; o < 5; o++) { smn[o][w] = pm[o]; smx[o][w] = px[o]; }
        }
    }
    __syncthreads();   // covers sgrad fill AND partial writes
    if (threadIdx.x < 5) {
        int o = threadIdx.x;
        float a = smn[o][0], b = smx[o][0];
#pragma unroll
        for (int k = 1; k < 8; k++) { a = fminf(a, smn[o][k]); b = fmaxf(b, smx[o][k]); }
        fmn[o] = a; fmx[o] = b;
    }
    __syncthreads();

    // fold normalization into per-octave scale + shared bias
    float mixv = *mixp;
    const float amps[5] = {0.1f, 0.05f, 0.025f, 0.0125f, 0.00625f};
    float s[5], B = 0.0f;
#pragma unroll
    for (int o = 0; o < 5; o++) {
        float mnv = fmn[o], mxv = fmx[o];
        float inv = 1.0f / (mxv - mnv);
        float am = amps[o] * mixv;
        s[o] = 2.0f * am * inv;
        B += am * (-2.0f * mnv * inv - 1.0f);
    }

    int t = blockIdx.x * 256 + threadIdx.x;
    int i  = t >> 6;
    int j0 = (t & 63) << 4;

    RunConst r0 = run_const_sm<0>(sgrad, i, j0);
    RunConst r1 = run_const_sm<1>(sgrad, i, j0);
    RunConst r2 = run_const_sm<2>(sgrad, i, j0);
    RunConst r3 = run_const_sm<3>(sgrad, i, j0);
    RunConst r4 = run_const_sm<4>(sgrad, i, j0);

    int p4 = t << 2;   // 4 consecutive float4 per run
#pragma unroll
    for (int q = 0; q < 4; q++) {
        float v[4];
#pragma unroll
        for (int k = 0; k < 4; k++) {
            int j = j0 + q * 4 + k;
            float acc = B;
            acc = fmaf(run_eval<0>(r0, j), s[0], acc);
            acc = fmaf(run_eval<1>(r1, j), s[1], acc);
            acc = fmaf(run_eval<2>(r2, j), s[2], acc);
            acc = fmaf(run_eval<3>(r3, j), s[3], acc);
            acc = fmaf(run_eval<4>(r4, j), s[4], acc);
            v[k] = acc;
        }
        g_noise4[p4 + q] = make_float4(v[0], v[1], v[2], v[3]);
    }
}

// ---------------------------------------------------------------------------
// K3: HBM-bound streaming apply: out = clip(image + noise, 0, 1)
// (unchanged from the proven 57.2us version: 4 float4/thread, block-strided,
//  front-batched loads, streaming cache hints)
// ---------------------------------------------------------------------------
#define VPT 4
__global__ void __launch_bounds__(256) k_apply(const float4* __restrict__ img,
                                               float4* __restrict__ out, int n4) {
    int base = blockIdx.x * (256 * VPT) + threadIdx.x;

    if (base + 3 * 256 < n4) {
        float4 v0 = __ldcs(img + base);
        float4 v1 = __ldcs(img + base + 256);
        float4 v2 = __ldcs(img + base + 512);
        float4 v3 = __ldcs(img + base + 768);
        float4 n0 = g_noise4[(base)       & (NPIX4 - 1)];
        float4 n1 = g_noise4[(base + 256) & (NPIX4 - 1)];
        float4 n2 = g_noise4[(base + 512) & (NPIX4 - 1)];
        float4 n3 = g_noise4[(base + 768) & (NPIX4 - 1)];

        v0.x = fminf(fmaxf(v0.x + n0.x, 0.0f), 1.0f);
        v0.y = fminf(fmaxf(v0.y + n0.y, 0.0f), 1.0f);
        v0.z = fminf(fmaxf(v0.z + n0.z, 0.0f), 1.0f);
        v0.w = fminf(fmaxf(v0.w + n0.w, 0.0f), 1.0f);
        v1.x = fminf(fmaxf(v1.x + n1.x, 0.0f), 1.0f);
        v1.y = fminf(fmaxf(v1.y + n1.y, 0.0f), 1.0f);
        v1.z = fminf(fmaxf(v1.z + n1.z, 0.0f), 1.0f);
        v1.w = fminf(fmaxf(v1.w + n1.w, 0.0f), 1.0f);
        v2.x = fminf(fmaxf(v2.x + n2.x, 0.0f), 1.0f);
        v2.y = fminf(fmaxf(v2.y + n2.y, 0.0f), 1.0f);
        v2.z = fminf(fmaxf(v2.z + n2.z, 0.0f), 1.0f);
        v2.w = fminf(fmaxf(v2.w + n2.w, 0.0f), 1.0f);
        v3.x = fminf(fmaxf(v3.x + n3.x, 0.0f), 1.0f);
        v3.y = fminf(fmaxf(v3.y + n3.y, 0.0f), 1.0f);
        v3.z = fminf(fmaxf(v3.z + n3.z, 0.0f), 1.0f);
        v3.w = fminf(fmaxf(v3.w + n3.w, 0.0f), 1.0f);

        __stcs(out + base,       v0);
        __stcs(out + base + 256, v1);
        __stcs(out + base + 512, v2);
        __stcs(out + base + 768, v3);
    } else {
        for (int k = 0; k < VPT; k++) {
            int idx = base + k * 256;
            if (idx >= n4) break;
            float4 nz = g_noise4[idx & (NPIX4 - 1)];
            float4 v = __ldcs(img + idx);
            v.x = fminf(fmaxf(v.x + nz.x, 0.0f), 1.0f);
            v.y = fminf(fmaxf(v.y + nz.y, 0.0f), 1.0f);
            v.z = fminf(fmaxf(v.z + nz.z, 0.0f), 1.0f);
            v.w = fminf(fmaxf(v.w + nz.w, 0.0f), 1.0f);
            __stcs(out + idx, v);
        }
    }
}

// ---------------------------------------------------------------------------
extern "C" void kernel_launch(void* const* d_in, const int* in_sizes, int n_in,
                              void* d_out, int out_size) {
    const float* image = nullptr;
    const float* mixp  = nullptr;
    const float* ang[5] = {nullptr, nullptr, nullptr, nullptr, nullptr};

    for (int k = 0; k < n_in; k++) {
        int s = in_sizes[k];
        const float* p = (const float*)d_in[k];
        if      (s == 1)    mixp   = p;
        else if (s == 25)   ang[0] = p;
        else if (s == 81)   ang[1] = p;
        else if (s == 289)  ang[2] = p;
        else if (s == 1089) ang[3] = p;
        else if (s == 4225) ang[4] = p;
        else                image  = p;   // 16*3*1024*1024
    }

    k_minmax<<<NBLK, 256>>>(ang[0], ang[1], ang[2], ang[3], ang[4]);
    k_noise<<<NBLK, 256>>>(ang[0], ang[1], ang[2], ang[3], ang[4], mixp);

    int n4 = out_size / 4;
    int blocks = (n4 + 256 * VPT - 1) / (256 * VPT);
    k_apply<<<blocks, 256>>>((const float4*)image, (float4*)d_out, n4);
}